// round 1
// baseline (speedup 1.0000x reference)
#include <cuda_runtime.h>
#include <cuda_bf16.h>
#include <math.h>

// ---------------------------------------------------------------------------
// Problem constants
// ---------------------------------------------------------------------------
#define BB   8
#define SS   1024
#define DD   1024
#define HH   16
#define DK   64
#define DFF  4096
#define MTOT (BB * SS)          // 8192 rows

// ---------------------------------------------------------------------------
// Scratch (device globals; no allocation allowed)
// ---------------------------------------------------------------------------
__device__ float g_q  [MTOT * DD];
__device__ float g_k  [MTOT * DD];
__device__ float g_v  [MTOT * DD];
__device__ float g_ctx[MTOT * DD];
__device__ float g_t  [MTOT * DD];
__device__ float g_y1 [MTOT * DD];
__device__ float g_h  [MTOT * DFF];

// ---------------------------------------------------------------------------
// SGEMM: C[M,N] = A[M,K] @ W[K,N] + bias (+ res) (ReLU optional)
// BM=BN=128, BK=16, 256 threads, 8x8 per thread split into 2x(4) x 2x(4)
// ---------------------------------------------------------------------------
template<int RELU, int HAS_RES>
__global__ __launch_bounds__(256)
void sgemm_kernel(const float* __restrict__ A,
                  const float* __restrict__ W,
                  const float* __restrict__ bias,
                  const float* __restrict__ res,
                  float* __restrict__ C,
                  int M, int N, int K)
{
    __shared__ float As[16][128];   // stored transposed: As[k][m]
    __shared__ float Bs[16][128];   // natural: Bs[k][n]

    const int t  = threadIdx.x;
    const int tx = t & 15;          // 16 thread cols
    const int ty = t >> 4;          // 16 thread rows
    const int rowBase = blockIdx.y * 128;
    const int colBase = blockIdx.x * 128;

    float acc[8][8];
    #pragma unroll
    for (int i = 0; i < 8; ++i)
        #pragma unroll
        for (int j = 0; j < 8; ++j) acc[i][j] = 0.0f;

    const int nk = K >> 4;
    for (int kt = 0; kt < nk; ++kt) {
        // ---- load tiles ----
        #pragma unroll
        for (int i = 0; i < 2; ++i) {
            int idx = t + i * 256;
            // A tile: 128 rows x 16 k, as float4 along K, stored transposed
            int r  = idx >> 2;
            int c4 = (idx & 3) << 2;
            float4 va = *(const float4*)(A + (size_t)(rowBase + r) * K + kt * 16 + c4);
            As[c4 + 0][r] = va.x;
            As[c4 + 1][r] = va.y;
            As[c4 + 2][r] = va.z;
            As[c4 + 3][r] = va.w;
            // B tile: 16 k rows x 128 n
            int kr = idx >> 5;
            int cc = (idx & 31) << 2;
            *(float4*)&Bs[kr][cc] =
                *(const float4*)(W + (size_t)(kt * 16 + kr) * N + colBase + cc);
        }
        __syncthreads();

        // ---- compute ----
        #pragma unroll
        for (int k = 0; k < 16; ++k) {
            float av[8], bv[8];
            *(float4*)&av[0] = *(float4*)&As[k][ty * 4];
            *(float4*)&av[4] = *(float4*)&As[k][ty * 4 + 64];
            *(float4*)&bv[0] = *(float4*)&Bs[k][tx * 4];
            *(float4*)&bv[4] = *(float4*)&Bs[k][tx * 4 + 64];
            #pragma unroll
            for (int i = 0; i < 8; ++i)
                #pragma unroll
                for (int j = 0; j < 8; ++j)
                    acc[i][j] = fmaf(av[i], bv[j], acc[i][j]);
        }
        __syncthreads();
    }

    // ---- epilogue ----
    #pragma unroll
    for (int ri = 0; ri < 2; ++ri) {
        #pragma unroll
        for (int i = 0; i < 4; ++i) {
            int row = rowBase + ty * 4 + ri * 64 + i;
            #pragma unroll
            for (int cj = 0; cj < 2; ++cj) {
                int col = colBase + tx * 4 + cj * 64;
                float4 v;
                v.x = acc[ri * 4 + i][cj * 4 + 0];
                v.y = acc[ri * 4 + i][cj * 4 + 1];
                v.z = acc[ri * 4 + i][cj * 4 + 2];
                v.w = acc[ri * 4 + i][cj * 4 + 3];
                float4 b4 = *(const float4*)(bias + col);
                v.x += b4.x; v.y += b4.y; v.z += b4.z; v.w += b4.w;
                if (HAS_RES) {
                    float4 r4 = *(const float4*)(res + (size_t)row * N + col);
                    v.x += r4.x; v.y += r4.y; v.z += r4.z; v.w += r4.w;
                }
                if (RELU) {
                    v.x = fmaxf(v.x, 0.0f); v.y = fmaxf(v.y, 0.0f);
                    v.z = fmaxf(v.z, 0.0f); v.w = fmaxf(v.w, 0.0f);
                }
                *(float4*)(C + (size_t)row * N + col) = v;
            }
        }
    }
}

// ---------------------------------------------------------------------------
// Flash attention (fp32). One block per (q-tile 64, head, batch).
// Q,K stored d-major (transposed) in smem, pitch 68; V,P natural, pitch 68.
// 256 threads = 16x16; each thread owns 4 q-rows x 4 cols.
// ---------------------------------------------------------------------------
#define FA_PITCH 68
#define FA_TILE  (64 * FA_PITCH)
#define FA_SMEM_BYTES (4 * FA_TILE * 4 + 256)

__global__ __launch_bounds__(256)
void flash_kernel(const float* __restrict__ Q,
                  const float* __restrict__ K,
                  const float* __restrict__ V,
                  const int*   __restrict__ mask,
                  float* __restrict__ Octx)
{
    extern __shared__ float sm[];
    float* Qt = sm;                 // [d][r]
    float* Kt = sm + FA_TILE;       // [d][r]
    float* Vs = sm + 2 * FA_TILE;   // [k][d]
    float* Ps = sm + 3 * FA_TILE;   // [q][k]
    int*   mk = (int*)(sm + 4 * FA_TILE);

    const int b  = blockIdx.z;
    const int h  = blockIdx.y;
    const int qb = blockIdx.x * 64;
    const int t  = threadIdx.x;
    const int tx = t & 15;
    const int ty = t >> 4;
    const float scale = 0.125f;     // 1/sqrt(64)

    // ---- load Q tile, transposed + pre-scaled ----
    const float* qptr = Q + ((size_t)b * SS + qb) * DD + h * DK;
    #pragma unroll
    for (int i = 0; i < 4; ++i) {
        int lin = t + i * 256;
        int r   = lin >> 4;
        int c4  = (lin & 15) << 2;
        float4 v = *(const float4*)(qptr + (size_t)r * DD + c4);
        Qt[(c4 + 0) * FA_PITCH + r] = v.x * scale;
        Qt[(c4 + 1) * FA_PITCH + r] = v.y * scale;
        Qt[(c4 + 2) * FA_PITCH + r] = v.z * scale;
        Qt[(c4 + 3) * FA_PITCH + r] = v.w * scale;
    }

    float m_i[4], l_i[4], o[4][4];
    #pragma unroll
    for (int i = 0; i < 4; ++i) {
        m_i[i] = -INFINITY;
        l_i[i] = 0.0f;
        #pragma unroll
        for (int j = 0; j < 4; ++j) o[i][j] = 0.0f;
    }

    for (int kt = 0; kt < SS / 64; ++kt) {
        __syncthreads();            // protect smem from previous iter readers
        const int kb = kt * 64;
        const float* kptr = K + ((size_t)b * SS + kb) * DD + h * DK;
        const float* vptr = V + ((size_t)b * SS + kb) * DD + h * DK;
        #pragma unroll
        for (int i = 0; i < 4; ++i) {
            int lin = t + i * 256;
            int r   = lin >> 4;
            int c4  = (lin & 15) << 2;
            float4 kv = *(const float4*)(kptr + (size_t)r * DD + c4);
            Kt[(c4 + 0) * FA_PITCH + r] = kv.x;
            Kt[(c4 + 1) * FA_PITCH + r] = kv.y;
            Kt[(c4 + 2) * FA_PITCH + r] = kv.z;
            Kt[(c4 + 3) * FA_PITCH + r] = kv.w;
            float4 vv = *(const float4*)(vptr + (size_t)r * DD + c4);
            *(float4*)&Vs[r * FA_PITCH + c4] = vv;
        }
        if (t < 64) mk[t] = mask[(size_t)b * SS + kb + t];
        __syncthreads();

        // ---- S = Q K^T (scaled) ----
        float s[4][4];
        #pragma unroll
        for (int i = 0; i < 4; ++i)
            #pragma unroll
            for (int j = 0; j < 4; ++j) s[i][j] = 0.0f;

        #pragma unroll 4
        for (int d = 0; d < 64; ++d) {
            float4 ra = *(float4*)&Qt[d * FA_PITCH + ty * 4];
            float4 rb = *(float4*)&Kt[d * FA_PITCH + tx * 4];
            float av[4] = {ra.x, ra.y, ra.z, ra.w};
            float bv[4] = {rb.x, rb.y, rb.z, rb.w};
            #pragma unroll
            for (int i = 0; i < 4; ++i)
                #pragma unroll
                for (int j = 0; j < 4; ++j)
                    s[i][j] = fmaf(av[i], bv[j], s[i][j]);
        }

        // ---- mask ----
        #pragma unroll
        for (int j = 0; j < 4; ++j) {
            if (mk[tx * 4 + j] == 0) {
                #pragma unroll
                for (int i = 0; i < 4; ++i) s[i][j] = -1e9f;
            }
        }

        // ---- online softmax update (row groups of 16 lanes) ----
        #pragma unroll
        for (int i = 0; i < 4; ++i) {
            float mloc = fmaxf(fmaxf(s[i][0], s[i][1]), fmaxf(s[i][2], s[i][3]));
            #pragma unroll
            for (int off = 8; off >= 1; off >>= 1)
                mloc = fmaxf(mloc, __shfl_xor_sync(0xffffffffu, mloc, off));
            float mnew  = fmaxf(m_i[i], mloc);
            float alpha = __expf(m_i[i] - mnew);
            m_i[i] = mnew;
            float lloc = 0.0f;
            #pragma unroll
            for (int j = 0; j < 4; ++j) {
                float p = __expf(s[i][j] - mnew);
                s[i][j] = p;
                lloc += p;
            }
            #pragma unroll
            for (int off = 8; off >= 1; off >>= 1)
                lloc += __shfl_xor_sync(0xffffffffu, lloc, off);
            l_i[i] = l_i[i] * alpha + lloc;
            #pragma unroll
            for (int j = 0; j < 4; ++j) o[i][j] *= alpha;
        }

        // ---- write P tile ----
        #pragma unroll
        for (int i = 0; i < 4; ++i) {
            float4 p4 = make_float4(s[i][0], s[i][1], s[i][2], s[i][3]);
            *(float4*)&Ps[(ty * 4 + i) * FA_PITCH + tx * 4] = p4;
        }
        __syncthreads();

        // ---- O += P @ V ----
        #pragma unroll 4
        for (int j = 0; j < 64; ++j) {
            float4 vb = *(float4*)&Vs[j * FA_PITCH + tx * 4];
            #pragma unroll
            for (int i = 0; i < 4; ++i) {
                float pa = Ps[(ty * 4 + i) * FA_PITCH + j];
                o[i][0] = fmaf(pa, vb.x, o[i][0]);
                o[i][1] = fmaf(pa, vb.y, o[i][1]);
                o[i][2] = fmaf(pa, vb.z, o[i][2]);
                o[i][3] = fmaf(pa, vb.w, o[i][3]);
            }
        }
    }

    // ---- finalize & store ----
    float* optr = Octx + ((size_t)b * SS + qb) * DD + h * DK;
    #pragma unroll
    for (int i = 0; i < 4; ++i) {
        int r = ty * 4 + i;
        float inv = 1.0f / l_i[i];
        float4 v = make_float4(o[i][0] * inv, o[i][1] * inv,
                               o[i][2] * inv, o[i][3] * inv);
        *(float4*)(optr + (size_t)r * DD + tx * 4) = v;
    }
}

// ---------------------------------------------------------------------------
// LayerNorm over last dim (1024), one block (256 thr) per row. Biased var.
// ---------------------------------------------------------------------------
__global__ __launch_bounds__(256)
void ln_kernel(const float* __restrict__ in,
               const float* __restrict__ ga,
               const float* __restrict__ gb,
               float* __restrict__ out)
{
    __shared__ float rbuf[8];
    __shared__ float stat[2];
    const int row = blockIdx.x;
    const int t   = threadIdx.x;
    const float* p = in + (size_t)row * DD + t * 4;

    float4 x = *(const float4*)p;
    float s = x.x + x.y + x.z + x.w;
    #pragma unroll
    for (int off = 16; off >= 1; off >>= 1)
        s += __shfl_xor_sync(0xffffffffu, s, off);
    if ((t & 31) == 0) rbuf[t >> 5] = s;
    __syncthreads();
    if (t == 0) {
        float v = 0.0f;
        #pragma unroll
        for (int w = 0; w < 8; ++w) v += rbuf[w];
        stat[0] = v;
    }
    __syncthreads();
    const float mean = stat[0] * (1.0f / 1024.0f);

    float dx0 = x.x - mean, dx1 = x.y - mean, dx2 = x.z - mean, dx3 = x.w - mean;
    float sq = dx0 * dx0 + dx1 * dx1 + dx2 * dx2 + dx3 * dx3;
    #pragma unroll
    for (int off = 16; off >= 1; off >>= 1)
        sq += __shfl_xor_sync(0xffffffffu, sq, off);
    if ((t & 31) == 0) rbuf[t >> 5] = sq;
    __syncthreads();
    if (t == 0) {
        float v = 0.0f;
        #pragma unroll
        for (int w = 0; w < 8; ++w) v += rbuf[w];
        stat[1] = v;
    }
    __syncthreads();
    const float var  = stat[1] * (1.0f / 1024.0f);
    const float rstd = rsqrtf(var + 1e-6f);

    float4 a4 = *(const float4*)(ga + t * 4);
    float4 b4 = *(const float4*)(gb + t * 4);
    float4 o;
    o.x = fmaf(a4.x, dx0 * rstd, b4.x);
    o.y = fmaf(a4.y, dx1 * rstd, b4.y);
    o.z = fmaf(a4.z, dx2 * rstd, b4.z);
    o.w = fmaf(a4.w, dx3 * rstd, b4.w);
    *(float4*)(out + (size_t)row * DD + t * 4) = o;
}

// ---------------------------------------------------------------------------
// Host launch
// ---------------------------------------------------------------------------
extern "C" void kernel_launch(void* const* d_in, const int* in_sizes, int n_in,
                              void* d_out, int out_size)
{
    const float* x     = (const float*)d_in[0];
    const int*   mask  = (const int*)  d_in[1];
    const float* wq    = (const float*)d_in[2];
    const float* bq    = (const float*)d_in[3];
    const float* wk    = (const float*)d_in[4];
    const float* bk    = (const float*)d_in[5];
    const float* wv    = (const float*)d_in[6];
    const float* bv    = (const float*)d_in[7];
    const float* wo    = (const float*)d_in[8];
    const float* bo    = (const float*)d_in[9];
    const float* ln1a  = (const float*)d_in[10];
    const float* ln1b  = (const float*)d_in[11];
    const float* ln2a  = (const float*)d_in[12];
    const float* ln2b  = (const float*)d_in[13];
    const float* w1    = (const float*)d_in[14];
    const float* b1    = (const float*)d_in[15];
    const float* w2    = (const float*)d_in[16];
    const float* b2    = (const float*)d_in[17];
    float* out = (float*)d_out;

    float *q, *k, *v, *ctx, *tb, *y1, *hb;
    cudaGetSymbolAddress((void**)&q,   g_q);
    cudaGetSymbolAddress((void**)&k,   g_k);
    cudaGetSymbolAddress((void**)&v,   g_v);
    cudaGetSymbolAddress((void**)&ctx, g_ctx);
    cudaGetSymbolAddress((void**)&tb,  g_t);
    cudaGetSymbolAddress((void**)&y1,  g_y1);
    cudaGetSymbolAddress((void**)&hb,  g_h);

    cudaFuncSetAttribute(flash_kernel,
                         cudaFuncAttributeMaxDynamicSharedMemorySize,
                         FA_SMEM_BYTES);

    dim3 gD(DD / 128, MTOT / 128);      // N=1024 GEMMs
    dim3 gF(DFF / 128, MTOT / 128);     // N=4096 GEMM
    dim3 blk(256);

    // QKV projections
    sgemm_kernel<0, 0><<<gD, blk>>>(x, wq, bq, nullptr, q, MTOT, DD, DD);
    sgemm_kernel<0, 0><<<gD, blk>>>(x, wk, bk, nullptr, k, MTOT, DD, DD);
    sgemm_kernel<0, 0><<<gD, blk>>>(x, wv, bv, nullptr, v, MTOT, DD, DD);

    // Attention
    dim3 gA(SS / 64, HH, BB);
    flash_kernel<<<gA, blk, FA_SMEM_BYTES>>>(q, k, v, mask, ctx);

    // Output projection + residual, LN1
    sgemm_kernel<0, 1><<<gD, blk>>>(ctx, wo, bo, x, tb, MTOT, DD, DD);
    ln_kernel<<<MTOT, blk>>>(tb, ln1a, ln1b, y1);

    // FFN
    sgemm_kernel<1, 0><<<gF, blk>>>(y1, w1, b1, nullptr, hb, MTOT, DFF, DD);
    sgemm_kernel<0, 1><<<gD, blk>>>(hb, w2, b2, y1, tb, MTOT, DD, DFF);
    ln_kernel<<<MTOT, blk>>>(tb, ln2a, ln2b, out);
}

// round 2
// speedup vs baseline: 1.8618x; 1.8618x over previous
#include <cuda_runtime.h>
#include <cuda_bf16.h>
#include <math.h>

// ---------------------------------------------------------------------------
// Problem constants
// ---------------------------------------------------------------------------
#define BB   8
#define SS   1024
#define DD   1024
#define HH   16
#define DK   64
#define DFF  4096
#define MTOT (BB * SS)          // 8192 rows

// ---------------------------------------------------------------------------
// Scratch (device globals; no allocation allowed)
// ---------------------------------------------------------------------------
__device__ float g_q  [MTOT * DD];
__device__ float g_k  [MTOT * DD];
__device__ float g_v  [MTOT * DD];
__device__ float g_ctx[MTOT * DD];
__device__ float g_t  [MTOT * DD];
__device__ float g_y1 [MTOT * DD];
__device__ float g_h  [MTOT * DFF];

// ---------------------------------------------------------------------------
// tf32 helpers
// ---------------------------------------------------------------------------
__device__ __forceinline__ unsigned cvt_tf32(float f) {
    unsigned u;
    asm("cvt.rna.tf32.f32 %0, %1;" : "=r"(u) : "f"(f));
    return u;
}

// ---------------------------------------------------------------------------
// TF32 MMA GEMM: C[M,N] = A[M,K] @ W[K,N] + bias (+res) (ReLU optional)
// BM=BN=128, BK=32. 256 threads = 8 warps (2x4), warp tile 64x32.
// mma.sync.m16n8k8 tf32, fp32 accumulate. Conflict-free smem fragment reads.
// ---------------------------------------------------------------------------
#define AP 36    // A smem pitch (floats)
#define BP 136   // B smem pitch (floats)

template<int RELU, int HAS_RES>
__global__ __launch_bounds__(256)
void mma_gemm(const float* __restrict__ A,
              const float* __restrict__ W,
              const float* __restrict__ bias,
              const float* __restrict__ res,
              float* __restrict__ C,
              int M, int N, int K)
{
    __shared__ unsigned As[128 * AP];   // [m][k], pitch 36
    __shared__ unsigned Bs[32 * BP];    // [k][n], pitch 136

    const int t    = threadIdx.x;
    const int lane = t & 31;
    const int wid  = t >> 5;
    const int warpM = wid & 1;          // 2 warp rows
    const int warpN = wid >> 1;         // 4 warp cols
    const int rowBase = blockIdx.y * 128;
    const int colBase = blockIdx.x * 128;

    float acc[4][4][4];
    #pragma unroll
    for (int a = 0; a < 4; ++a)
        #pragma unroll
        for (int b = 0; b < 4; ++b)
            #pragma unroll
            for (int c = 0; c < 4; ++c) acc[a][b][c] = 0.0f;

    float4 pa[4], pb[4];

    // ---- load tile kt into regs ----
    auto loadTile = [&](int kt) {
        #pragma unroll
        for (int i = 0; i < 4; ++i) {
            int idx = t + i * 256;
            pa[i] = *(const float4*)(A + (size_t)(rowBase + (idx >> 3)) * K
                                       + kt * 32 + ((idx & 7) << 2));
            pb[i] = *(const float4*)(W + (size_t)(kt * 32 + (idx >> 5)) * N
                                       + colBase + ((idx & 31) << 2));
        }
    };
    // ---- convert + store regs into smem ----
    auto storeTile = [&]() {
        #pragma unroll
        for (int i = 0; i < 4; ++i) {
            int idx = t + i * 256;
            int r = idx >> 3, c = (idx & 7) << 2;
            As[r * AP + c + 0] = cvt_tf32(pa[i].x);
            As[r * AP + c + 1] = cvt_tf32(pa[i].y);
            As[r * AP + c + 2] = cvt_tf32(pa[i].z);
            As[r * AP + c + 3] = cvt_tf32(pa[i].w);
            int kr = idx >> 5, cc = (idx & 31) << 2;
            Bs[kr * BP + cc + 0] = cvt_tf32(pb[i].x);
            Bs[kr * BP + cc + 1] = cvt_tf32(pb[i].y);
            Bs[kr * BP + cc + 2] = cvt_tf32(pb[i].z);
            Bs[kr * BP + cc + 3] = cvt_tf32(pb[i].w);
        }
    };

    loadTile(0);
    storeTile();
    __syncthreads();

    const int nk = K >> 5;
    for (int kt = 0; kt < nk; ++kt) {
        if (kt + 1 < nk) loadTile(kt + 1);

        #pragma unroll
        for (int ks = 0; ks < 4; ++ks) {
            const int k0 = ks * 8;
            unsigned af[4][4];
            #pragma unroll
            for (int mf = 0; mf < 4; ++mf) {
                int r = warpM * 64 + mf * 16 + (lane >> 2);
                int c = k0 + (lane & 3);
                af[mf][0] = As[r * AP + c];
                af[mf][1] = As[(r + 8) * AP + c];
                af[mf][2] = As[r * AP + c + 4];
                af[mf][3] = As[(r + 8) * AP + c + 4];
            }
            #pragma unroll
            for (int nf = 0; nf < 4; ++nf) {
                int n  = warpN * 32 + nf * 8 + (lane >> 2);
                int kk = k0 + (lane & 3);
                unsigned b0 = Bs[kk * BP + n];
                unsigned b1 = Bs[(kk + 4) * BP + n];
                #pragma unroll
                for (int mf = 0; mf < 4; ++mf) {
                    asm volatile(
                        "mma.sync.aligned.m16n8k8.row.col.f32.tf32.tf32.f32 "
                        "{%0,%1,%2,%3}, {%4,%5,%6,%7}, {%8,%9}, {%0,%1,%2,%3};\n"
                        : "+f"(acc[mf][nf][0]), "+f"(acc[mf][nf][1]),
                          "+f"(acc[mf][nf][2]), "+f"(acc[mf][nf][3])
                        : "r"(af[mf][0]), "r"(af[mf][1]),
                          "r"(af[mf][2]), "r"(af[mf][3]),
                          "r"(b0), "r"(b1));
                }
            }
        }
        __syncthreads();
        if (kt + 1 < nk) {
            storeTile();
            __syncthreads();
        }
    }

    // ---- epilogue ----
    #pragma unroll
    for (int mf = 0; mf < 4; ++mf) {
        int r0 = rowBase + warpM * 64 + mf * 16 + (lane >> 2);
        #pragma unroll
        for (int nf = 0; nf < 4; ++nf) {
            int c0 = colBase + warpN * 32 + nf * 8 + ((lane & 3) << 1);
            float2 b2 = *(const float2*)(bias + c0);
            float v0 = acc[mf][nf][0] + b2.x;
            float v1 = acc[mf][nf][1] + b2.y;
            float v2 = acc[mf][nf][2] + b2.x;
            float v3 = acc[mf][nf][3] + b2.y;
            if (HAS_RES) {
                float2 ra = *(const float2*)(res + (size_t)r0 * N + c0);
                float2 rb = *(const float2*)(res + (size_t)(r0 + 8) * N + c0);
                v0 += ra.x; v1 += ra.y; v2 += rb.x; v3 += rb.y;
            }
            if (RELU) {
                v0 = fmaxf(v0, 0.0f); v1 = fmaxf(v1, 0.0f);
                v2 = fmaxf(v2, 0.0f); v3 = fmaxf(v3, 0.0f);
            }
            *(float2*)(C + (size_t)r0 * N + c0)       = make_float2(v0, v1);
            *(float2*)(C + (size_t)(r0 + 8) * N + c0) = make_float2(v2, v3);
        }
    }
}

// ---------------------------------------------------------------------------
// Flash attention (fp32). One block per (q-tile 64, head, batch). (unchanged)
// ---------------------------------------------------------------------------
#define FA_PITCH 68
#define FA_TILE  (64 * FA_PITCH)
#define FA_SMEM_BYTES (4 * FA_TILE * 4 + 256)

__global__ __launch_bounds__(256)
void flash_kernel(const float* __restrict__ Q,
                  const float* __restrict__ K,
                  const float* __restrict__ V,
                  const int*   __restrict__ mask,
                  float* __restrict__ Octx)
{
    extern __shared__ float sm[];
    float* Qt = sm;                 // [d][r]
    float* Kt = sm + FA_TILE;       // [d][r]
    float* Vs = sm + 2 * FA_TILE;   // [k][d]
    float* Ps = sm + 3 * FA_TILE;   // [q][k]
    int*   mk = (int*)(sm + 4 * FA_TILE);

    const int b  = blockIdx.z;
    const int h  = blockIdx.y;
    const int qb = blockIdx.x * 64;
    const int t  = threadIdx.x;
    const int tx = t & 15;
    const int ty = t >> 4;
    const float scale = 0.125f;     // 1/sqrt(64)

    const float* qptr = Q + ((size_t)b * SS + qb) * DD + h * DK;
    #pragma unroll
    for (int i = 0; i < 4; ++i) {
        int lin = t + i * 256;
        int r   = lin >> 4;
        int c4  = (lin & 15) << 2;
        float4 v = *(const float4*)(qptr + (size_t)r * DD + c4);
        Qt[(c4 + 0) * FA_PITCH + r] = v.x * scale;
        Qt[(c4 + 1) * FA_PITCH + r] = v.y * scale;
        Qt[(c4 + 2) * FA_PITCH + r] = v.z * scale;
        Qt[(c4 + 3) * FA_PITCH + r] = v.w * scale;
    }

    float m_i[4], l_i[4], o[4][4];
    #pragma unroll
    for (int i = 0; i < 4; ++i) {
        m_i[i] = -INFINITY;
        l_i[i] = 0.0f;
        #pragma unroll
        for (int j = 0; j < 4; ++j) o[i][j] = 0.0f;
    }

    for (int kt = 0; kt < SS / 64; ++kt) {
        __syncthreads();
        const int kb = kt * 64;
        const float* kptr = K + ((size_t)b * SS + kb) * DD + h * DK;
        const float* vptr = V + ((size_t)b * SS + kb) * DD + h * DK;
        #pragma unroll
        for (int i = 0; i < 4; ++i) {
            int lin = t + i * 256;
            int r   = lin >> 4;
            int c4  = (lin & 15) << 2;
            float4 kv = *(const float4*)(kptr + (size_t)r * DD + c4);
            Kt[(c4 + 0) * FA_PITCH + r] = kv.x;
            Kt[(c4 + 1) * FA_PITCH + r] = kv.y;
            Kt[(c4 + 2) * FA_PITCH + r] = kv.z;
            Kt[(c4 + 3) * FA_PITCH + r] = kv.w;
            float4 vv = *(const float4*)(vptr + (size_t)r * DD + c4);
            *(float4*)&Vs[r * FA_PITCH + c4] = vv;
        }
        if (t < 64) mk[t] = mask[(size_t)b * SS + kb + t];
        __syncthreads();

        float s[4][4];
        #pragma unroll
        for (int i = 0; i < 4; ++i)
            #pragma unroll
            for (int j = 0; j < 4; ++j) s[i][j] = 0.0f;

        #pragma unroll 4
        for (int d = 0; d < 64; ++d) {
            float4 ra = *(float4*)&Qt[d * FA_PITCH + ty * 4];
            float4 rb = *(float4*)&Kt[d * FA_PITCH + tx * 4];
            float av[4] = {ra.x, ra.y, ra.z, ra.w};
            float bv[4] = {rb.x, rb.y, rb.z, rb.w};
            #pragma unroll
            for (int i = 0; i < 4; ++i)
                #pragma unroll
                for (int j = 0; j < 4; ++j)
                    s[i][j] = fmaf(av[i], bv[j], s[i][j]);
        }

        #pragma unroll
        for (int j = 0; j < 4; ++j) {
            if (mk[tx * 4 + j] == 0) {
                #pragma unroll
                for (int i = 0; i < 4; ++i) s[i][j] = -1e9f;
            }
        }

        #pragma unroll
        for (int i = 0; i < 4; ++i) {
            float mloc = fmaxf(fmaxf(s[i][0], s[i][1]), fmaxf(s[i][2], s[i][3]));
            #pragma unroll
            for (int off = 8; off >= 1; off >>= 1)
                mloc = fmaxf(mloc, __shfl_xor_sync(0xffffffffu, mloc, off));
            float mnew  = fmaxf(m_i[i], mloc);
            float alpha = __expf(m_i[i] - mnew);
            m_i[i] = mnew;
            float lloc = 0.0f;
            #pragma unroll
            for (int j = 0; j < 4; ++j) {
                float p = __expf(s[i][j] - mnew);
                s[i][j] = p;
                lloc += p;
            }
            #pragma unroll
            for (int off = 8; off >= 1; off >>= 1)
                lloc += __shfl_xor_sync(0xffffffffu, lloc, off);
            l_i[i] = l_i[i] * alpha + lloc;
            #pragma unroll
            for (int j = 0; j < 4; ++j) o[i][j] *= alpha;
        }

        #pragma unroll
        for (int i = 0; i < 4; ++i) {
            float4 p4 = make_float4(s[i][0], s[i][1], s[i][2], s[i][3]);
            *(float4*)&Ps[(ty * 4 + i) * FA_PITCH + tx * 4] = p4;
        }
        __syncthreads();

        #pragma unroll 4
        for (int j = 0; j < 64; ++j) {
            float4 vb = *(float4*)&Vs[j * FA_PITCH + tx * 4];
            #pragma unroll
            for (int i = 0; i < 4; ++i) {
                float pa = Ps[(ty * 4 + i) * FA_PITCH + j];
                o[i][0] = fmaf(pa, vb.x, o[i][0]);
                o[i][1] = fmaf(pa, vb.y, o[i][1]);
                o[i][2] = fmaf(pa, vb.z, o[i][2]);
                o[i][3] = fmaf(pa, vb.w, o[i][3]);
            }
        }
    }

    float* optr = Octx + ((size_t)b * SS + qb) * DD + h * DK;
    #pragma unroll
    for (int i = 0; i < 4; ++i) {
        int r = ty * 4 + i;
        float inv = 1.0f / l_i[i];
        float4 v = make_float4(o[i][0] * inv, o[i][1] * inv,
                               o[i][2] * inv, o[i][3] * inv);
        *(float4*)(optr + (size_t)r * DD + tx * 4) = v;
    }
}

// ---------------------------------------------------------------------------
// LayerNorm over last dim (1024), one block (256 thr) per row. Biased var.
// ---------------------------------------------------------------------------
__global__ __launch_bounds__(256)
void ln_kernel(const float* __restrict__ in,
               const float* __restrict__ ga,
               const float* __restrict__ gb,
               float* __restrict__ out)
{
    __shared__ float rbuf[8];
    __shared__ float stat[2];
    const int row = blockIdx.x;
    const int t   = threadIdx.x;
    const float* p = in + (size_t)row * DD + t * 4;

    float4 x = *(const float4*)p;
    float s = x.x + x.y + x.z + x.w;
    #pragma unroll
    for (int off = 16; off >= 1; off >>= 1)
        s += __shfl_xor_sync(0xffffffffu, s, off);
    if ((t & 31) == 0) rbuf[t >> 5] = s;
    __syncthreads();
    if (t == 0) {
        float v = 0.0f;
        #pragma unroll
        for (int w = 0; w < 8; ++w) v += rbuf[w];
        stat[0] = v;
    }
    __syncthreads();
    const float mean = stat[0] * (1.0f / 1024.0f);

    float dx0 = x.x - mean, dx1 = x.y - mean, dx2 = x.z - mean, dx3 = x.w - mean;
    float sq = dx0 * dx0 + dx1 * dx1 + dx2 * dx2 + dx3 * dx3;
    #pragma unroll
    for (int off = 16; off >= 1; off >>= 1)
        sq += __shfl_xor_sync(0xffffffffu, sq, off);
    if ((t & 31) == 0) rbuf[t >> 5] = sq;
    __syncthreads();
    if (t == 0) {
        float v = 0.0f;
        #pragma unroll
        for (int w = 0; w < 8; ++w) v += rbuf[w];
        stat[1] = v;
    }
    __syncthreads();
    const float var  = stat[1] * (1.0f / 1024.0f);
    const float rstd = rsqrtf(var + 1e-6f);

    float4 a4 = *(const float4*)(ga + t * 4);
    float4 b4 = *(const float4*)(gb + t * 4);
    float4 o;
    o.x = fmaf(a4.x, dx0 * rstd, b4.x);
    o.y = fmaf(a4.y, dx1 * rstd, b4.y);
    o.z = fmaf(a4.z, dx2 * rstd, b4.z);
    o.w = fmaf(a4.w, dx3 * rstd, b4.w);
    *(float4*)(out + (size_t)row * DD + t * 4) = o;
}

// ---------------------------------------------------------------------------
// Host launch
// ---------------------------------------------------------------------------
extern "C" void kernel_launch(void* const* d_in, const int* in_sizes, int n_in,
                              void* d_out, int out_size)
{
    const float* x     = (const float*)d_in[0];
    const int*   mask  = (const int*)  d_in[1];
    const float* wq    = (const float*)d_in[2];
    const float* bq    = (const float*)d_in[3];
    const float* wk    = (const float*)d_in[4];
    const float* bk    = (const float*)d_in[5];
    const float* wv    = (const float*)d_in[6];
    const float* bv    = (const float*)d_in[7];
    const float* wo    = (const float*)d_in[8];
    const float* bo    = (const float*)d_in[9];
    const float* ln1a  = (const float*)d_in[10];
    const float* ln1b  = (const float*)d_in[11];
    const float* ln2a  = (const float*)d_in[12];
    const float* ln2b  = (const float*)d_in[13];
    const float* w1    = (const float*)d_in[14];
    const float* b1    = (const float*)d_in[15];
    const float* w2    = (const float*)d_in[16];
    const float* b2    = (const float*)d_in[17];
    float* out = (float*)d_out;

    float *q, *k, *v, *ctx, *tb, *y1, *hb;
    cudaGetSymbolAddress((void**)&q,   g_q);
    cudaGetSymbolAddress((void**)&k,   g_k);
    cudaGetSymbolAddress((void**)&v,   g_v);
    cudaGetSymbolAddress((void**)&ctx, g_ctx);
    cudaGetSymbolAddress((void**)&tb,  g_t);
    cudaGetSymbolAddress((void**)&y1,  g_y1);
    cudaGetSymbolAddress((void**)&hb,  g_h);

    cudaFuncSetAttribute(flash_kernel,
                         cudaFuncAttributeMaxDynamicSharedMemorySize,
                         FA_SMEM_BYTES);

    dim3 gD(DD / 128, MTOT / 128);      // N=1024 GEMMs
    dim3 gF(DFF / 128, MTOT / 128);     // N=4096 GEMM
    dim3 blk(256);

    // QKV projections (tf32 MMA)
    mma_gemm<0, 0><<<gD, blk>>>(x, wq, bq, nullptr, q, MTOT, DD, DD);
    mma_gemm<0, 0><<<gD, blk>>>(x, wk, bk, nullptr, k, MTOT, DD, DD);
    mma_gemm<0, 0><<<gD, blk>>>(x, wv, bv, nullptr, v, MTOT, DD, DD);

    // Attention
    dim3 gA(SS / 64, HH, BB);
    flash_kernel<<<gA, blk, FA_SMEM_BYTES>>>(q, k, v, mask, ctx);

    // Output projection + residual, LN1
    mma_gemm<0, 1><<<gD, blk>>>(ctx, wo, bo, x, tb, MTOT, DD, DD);
    ln_kernel<<<MTOT, blk>>>(tb, ln1a, ln1b, y1);

    // FFN
    mma_gemm<1, 0><<<gF, blk>>>(y1, w1, b1, nullptr, hb, MTOT, DFF, DD);
    mma_gemm<0, 1><<<gD, blk>>>(hb, w2, b2, y1, tb, MTOT, DD, DFF);
    ln_kernel<<<MTOT, blk>>>(tb, ln2a, ln2b, out);
}